// round 1
// baseline (speedup 1.0000x reference)
#include <cuda_runtime.h>
#include <cuda_bf16.h>
#include <cstdint>

// x: [B=64, C=12, 224, 224] fp32
// w: [C=12, E=768] fp32
// out: [B=64, P=196, E=768] fp32
//
// out[b, p, e] = sum_c ( sum_{16x16 patch p of channel c} x ) * w[c, e]

#define IMG   224
#define PATCH 16
#define NP    14      // patches per side
#define C_IN  12
#define EMBED 768
#define NTHREADS 384  // 12 warps: one warp per channel in the pooling phase

__global__ __launch_bounds__(NTHREADS) void patch_pool_embed_kernel(
    const float* __restrict__ x,
    const float* __restrict__ w,
    float* __restrict__ out)
{
    const int p   = blockIdx.x;          // 0..195
    const int b   = blockIdx.y;          // 0..63
    const int pi  = p / NP;
    const int pj  = p - pi * NP;
    const int tid = threadIdx.x;
    const int warp = tid >> 5;           // 0..11 == channel
    const int lane = tid & 31;

    __shared__ float pooled[C_IN];

    // ---- Phase 1: per-warp 16x16 sum-pool of channel `warp` ----
    // Patch row = 16 floats = 64 B, 64B-aligned. 4 lanes cover one row via float4;
    // 32 lanes cover 8 rows per iteration; 2 iterations cover 16 rows.
    const float* base = x
        + (((size_t)b * C_IN + warp) * IMG + (size_t)pi * PATCH) * IMG
        + (size_t)pj * PATCH;

    float s = 0.0f;
    #pragma unroll
    for (int k = 0; k < 2; ++k) {
        const int idx = lane + 32 * k;   // 0..63
        const int r   = idx >> 2;        // row 0..15
        const int q   = idx & 3;         // float4 index within row
        const float4 v = *reinterpret_cast<const float4*>(base + (size_t)r * IMG + q * 4);
        s += (v.x + v.y) + (v.z + v.w);
    }
    #pragma unroll
    for (int o = 16; o > 0; o >>= 1)
        s += __shfl_xor_sync(0xffffffffu, s, o);
    if (lane == 0) pooled[warp] = s;
    __syncthreads();

    // ---- Phase 2: tiny C->E contraction, 2 embedding columns per thread ----
    const int e0 = tid;
    const int e1 = tid + NTHREADS;       // 384 + tid, covers 768 total
    float acc0 = 0.0f, acc1 = 0.0f;
    #pragma unroll
    for (int c = 0; c < C_IN; ++c) {
        const float pc = pooled[c];
        acc0 = fmaf(pc, __ldg(&w[c * EMBED + e0]), acc0);
        acc1 = fmaf(pc, __ldg(&w[c * EMBED + e1]), acc1);
    }

    float* o = out + ((size_t)b * (NP * NP) + p) * EMBED;
    o[e0] = acc0;
    o[e1] = acc1;
}

extern "C" void kernel_launch(void* const* d_in, const int* in_sizes, int n_in,
                              void* d_out, int out_size)
{
    const float* x = (const float*)d_in[0];
    const float* w = (const float*)d_in[1];
    float* out = (float*)d_out;

    dim3 grid(NP * NP, 64);   // 196 x 64 = 12544 CTAs
    patch_pool_embed_kernel<<<grid, NTHREADS>>>(x, w, out);
}

// round 2
// speedup vs baseline: 1.1097x; 1.1097x over previous
#include <cuda_runtime.h>
#include <cuda_bf16.h>
#include <cstdint>

// x:   [B=64, C=12, 224, 224] fp32
// w:   [C=12, E=768] fp32
// out: [B=64, P=196, E=768] fp32
//
// out[b, p, e] = (sum of 16x16 patch p of channel c of x) dot w[c, e]
//
// CTA = (patch-pair, patch-row, batch). A pair of horizontally adjacent
// patches spans exactly one 128B cache line per image row -> full-line loads.

#define IMG   224
#define NP    14
#define C_IN  12
#define EMBED 768
#define NTHREADS 384   // 12 warps: one warp per channel in pooling phase

__global__ __launch_bounds__(NTHREADS) void patch_pool_embed_pair_kernel(
    const float* __restrict__ x,
    const float* __restrict__ w,
    float* __restrict__ out)
{
    const int pp  = blockIdx.x;          // patch pair 0..6
    const int pi  = blockIdx.y;          // 0..13
    const int b   = blockIdx.z;          // 0..63
    const int tid = threadIdx.x;
    const int warp = tid >> 5;           // channel 0..11
    const int lane = tid & 31;

    __shared__ float pooled[C_IN][2];

    // ---- Phase 1: warp `c` pools a 16x32 region (2 patches side by side) ----
    // Row segment = 32 floats = 128 B, 128B-aligned (row stride 896 B = 7*128).
    // 8 lanes (float4 each) cover one row; 32 lanes cover 4 rows per iter.
    const float* base = x
        + (((size_t)(b * C_IN + warp) * IMG) + (size_t)pi * 16) * IMG
        + (size_t)pp * 32;

    const int c4 = lane & 7;             // float4 slot within the 32-float row
    float s = 0.0f;
    #pragma unroll
    for (int k = 0; k < 4; ++k) {
        const int r = ((lane + 32 * k) >> 3);   // row 0..15
        const float4 v = *reinterpret_cast<const float4*>(base + (size_t)r * IMG + c4 * 4);
        s += (v.x + v.y) + (v.z + v.w);
    }
    // Reduce over bits {4,3,1,0} of lane; bit 2 (lane&4) selects the patch.
    s += __shfl_xor_sync(0xffffffffu, s, 16);
    s += __shfl_xor_sync(0xffffffffu, s, 8);
    s += __shfl_xor_sync(0xffffffffu, s, 2);
    s += __shfl_xor_sync(0xffffffffu, s, 1);
    if ((lane & 27) == 0)                 // lanes 0 (patch 0) and 4 (patch 1)
        pooled[warp][(lane >> 2) & 1] = s;
    __syncthreads();

    // ---- Phase 2: C->E contraction for both patches; 1 float4 out/thread ----
    const int pj = tid / 192;             // local patch 0 or 1 (uniform per warp)
    const int e0 = (tid % 192) * 4;       // embedding column base

    float pc[C_IN];
    #pragma unroll
    for (int c = 0; c < C_IN; ++c) pc[c] = pooled[c][pj];

    float4 acc = make_float4(0.f, 0.f, 0.f, 0.f);
    #pragma unroll
    for (int c = 0; c < C_IN; ++c) {
        const float4 wv = *reinterpret_cast<const float4*>(&w[c * EMBED + e0]);
        acc.x = fmaf(pc[c], wv.x, acc.x);
        acc.y = fmaf(pc[c], wv.y, acc.y);
        acc.z = fmaf(pc[c], wv.z, acc.z);
        acc.w = fmaf(pc[c], wv.w, acc.w);
    }

    float* o = out + (((size_t)b * (NP * NP)) + (size_t)pi * NP + pp * 2 + pj) * EMBED + e0;
    *reinterpret_cast<float4*>(o) = acc;
}

extern "C" void kernel_launch(void* const* d_in, const int* in_sizes, int n_in,
                              void* d_out, int out_size)
{
    const float* x = (const float*)d_in[0];
    const float* w = (const float*)d_in[1];
    float* out = (float*)d_out;

    dim3 grid(7, NP, 64);   // 6272 CTAs
    patch_pool_embed_pair_kernel<<<grid, NTHREADS>>>(x, w, out);
}